// round 2
// baseline (speedup 1.0000x reference)
#include <cuda_runtime.h>
#include <math.h>

#define NNODES 50000
#define NEDGES 500000
#define CDIM   128
#define K3C    384

// ---------------- scratch (device globals; no allocations allowed) ----------
__device__ float g_h  [NNODES * CDIM];
__device__ float g_m  [NNODES * CDIM];
__device__ float g_x  [NNODES * CDIM];
__device__ float g_agg[NNODES * CDIM];
__device__ float g_tot[NNODES * CDIM];
__device__ float g_gi [NNODES * K3C];
__device__ float g_gh [NNODES * K3C];
__device__ float g_z  [NNODES * CDIM];

// ---------------- feature build ---------------------------------------------
__global__ void build_features(const int* __restrict__ xt,
                               const int* __restrict__ xtok,
                               const float* __restrict__ xs) {
    int idx = blockIdx.x * blockDim.x + threadIdx.x;
    if (idx >= NNODES * CDIM) return;
    int n = idx >> 7;
    int c = idx & 127;
    float v;
    if (c < 32) {
        v = (c == xt[n]) ? 1.0f : 0.0f;
    } else if (c < 126) {
        int tok = xtok[n];
        tok = min(max(tok, 0), 93);
        v = ((c - 32) == tok) ? 1.0f : 0.0f;
    } else {
        v = xs[n * 2 + (c - 126)];
    }
    g_h[idx] = v;
}

// ---------------- fp32 SGEMM, K=128 fixed ------------------------------------
// TRANSB=0: B is [128, Ncols] row-major (C = A*B)
// TRANSB=1: B is [Ncols, 128] row-major (C = A*B^T)
// bias (len Ncols) optional; RELU optional epilogue.
template <int TRANSB, int RELU>
__global__ __launch_bounds__(256)
void sgemm128(const float* __restrict__ A, const float* __restrict__ B,
              const float* __restrict__ bias, float* __restrict__ C,
              int M, int Ncols) {
    __shared__ float As[16][129];
    __shared__ float Bs[16][129];
    const int tid  = threadIdx.x;
    const int brow = blockIdx.x * 128;
    const int bcol = blockIdx.y * 128;
    const int trow = (tid / 16) * 8;
    const int tcol = (tid % 16) * 8;
    float acc[8][8];
#pragma unroll
    for (int i = 0; i < 8; i++)
#pragma unroll
        for (int j = 0; j < 8; j++) acc[i][j] = 0.0f;

    for (int kt = 0; kt < 128; kt += 16) {
        // A tile: 128 x 16 -> As[k][row]
#pragma unroll
        for (int i = 0; i < 2; i++) {
            int q  = tid + 256 * i;
            int r  = q >> 2;
            int c4 = (q & 3) * 4;
            float4 v = make_float4(0.f, 0.f, 0.f, 0.f);
            int gr = brow + r;
            if (gr < M) v = *reinterpret_cast<const float4*>(A + (long)gr * 128 + kt + c4);
            As[c4 + 0][r] = v.x; As[c4 + 1][r] = v.y;
            As[c4 + 2][r] = v.z; As[c4 + 3][r] = v.w;
        }
        if (TRANSB) {
#pragma unroll
            for (int i = 0; i < 2; i++) {
                int q  = tid + 256 * i;
                int j  = q >> 2;
                int c4 = (q & 3) * 4;
                float4 v = *reinterpret_cast<const float4*>(B + (long)(bcol + j) * 128 + kt + c4);
                Bs[c4 + 0][j] = v.x; Bs[c4 + 1][j] = v.y;
                Bs[c4 + 2][j] = v.z; Bs[c4 + 3][j] = v.w;
            }
        } else {
#pragma unroll
            for (int i = 0; i < 2; i++) {
                int q  = tid + 256 * i;
                int kr = q >> 5;
                int c4 = (q & 31) * 4;
                float4 v = *reinterpret_cast<const float4*>(B + (long)(kt + kr) * Ncols + bcol + c4);
                Bs[kr][c4 + 0] = v.x; Bs[kr][c4 + 1] = v.y;
                Bs[kr][c4 + 2] = v.z; Bs[kr][c4 + 3] = v.w;
            }
        }
        __syncthreads();
#pragma unroll
        for (int k = 0; k < 16; k++) {
            float ra[8], rb[8];
#pragma unroll
            for (int i = 0; i < 8; i++) ra[i] = As[k][trow + i];
#pragma unroll
            for (int j = 0; j < 8; j++) rb[j] = Bs[k][tcol + j];
#pragma unroll
            for (int i = 0; i < 8; i++)
#pragma unroll
                for (int j = 0; j < 8; j++) acc[i][j] += ra[i] * rb[j];
        }
        __syncthreads();
    }

#pragma unroll
    for (int i = 0; i < 8; i++) {
        int gr = brow + trow + i;
        if (gr >= M) break;
#pragma unroll
        for (int j = 0; j < 8; j += 4) {
            float4 v;
            v.x = acc[i][j + 0]; v.y = acc[i][j + 1];
            v.z = acc[i][j + 2]; v.w = acc[i][j + 3];
            if (bias != nullptr) {
                v.x += bias[bcol + tcol + j + 0];
                v.y += bias[bcol + tcol + j + 1];
                v.z += bias[bcol + tcol + j + 2];
                v.w += bias[bcol + tcol + j + 3];
            }
            if (RELU) {
                v.x = fmaxf(v.x, 0.f); v.y = fmaxf(v.y, 0.f);
                v.z = fmaxf(v.z, 0.f); v.w = fmaxf(v.w, 0.f);
            }
            *reinterpret_cast<float4*>(C + (long)gr * Ncols + bcol + tcol + j) = v;
        }
    }
}

// ---------------- scatter-add (one warp per edge, lane = 4 channels) ---------
__global__ void scatter_add(const int* __restrict__ ei, const int* __restrict__ et, int t) {
    long idx = (long)blockIdx.x * blockDim.x + threadIdx.x;
    int e = (int)(idx >> 5);
    if (e >= NEDGES) return;
    if (et[e] != t) return;
    int lane = (int)(idx & 31);
    int s = ei[e];
    int d = ei[NEDGES + e];
    float4 v = *reinterpret_cast<const float4*>(g_x + (long)s * 128 + lane * 4);
    float* o = g_agg + (long)d * 128 + lane * 4;
    atomicAdd(o + 0, v.x);
    atomicAdd(o + 1, v.y);
    atomicAdd(o + 2, v.z);
    atomicAdd(o + 3, v.w);
}

// ---------------- GRU gate (r,z,n ordering, torch GRUCell) -------------------
__global__ void gru_gate() {
    int idx = blockIdx.x * blockDim.x + threadIdx.x;
    if (idx >= NNODES * CDIM) return;
    int n = idx >> 7;
    int c = idx & 127;
    const float* gi = g_gi + (long)n * K3C;
    const float* gh = g_gh + (long)n * K3C;
    float r  = 1.0f / (1.0f + expf(-(gi[c]       + gh[c])));
    float z  = 1.0f / (1.0f + expf(-(gi[128 + c] + gh[128 + c])));
    float ng = tanhf(gi[256 + c] + r * gh[256 + c]);
    float h  = g_m[idx];
    g_m[idx] = (1.0f - z) * ng + z * h;
}

__global__ void add_total() {
    int idx = blockIdx.x * blockDim.x + threadIdx.x;
    if (idx >= NNODES * CDIM) return;
    g_tot[idx] += g_m[idx];
}

// ---------------- LayerNorm(residual) + ReLU ---------------------------------
__global__ void ln_relu(const float* __restrict__ gam, const float* __restrict__ bet) {
    int n = blockIdx.x;
    int c = threadIdx.x;
    float v  = g_h[(long)n * 128 + c] + g_tot[(long)n * 128 + c];
    float s  = v;
    float s2 = v * v;
#pragma unroll
    for (int o = 16; o; o >>= 1) {
        s  += __shfl_xor_sync(0xffffffffu, s,  o);
        s2 += __shfl_xor_sync(0xffffffffu, s2, o);
    }
    __shared__ float sh[4], sh2[4];
    int w = c >> 5;
    if ((c & 31) == 0) { sh[w] = s; sh2[w] = s2; }
    __syncthreads();
    s  = sh[0] + sh[1] + sh[2] + sh[3];
    s2 = sh2[0] + sh2[1] + sh2[2] + sh2[3];
    float mu  = s * (1.0f / 128.0f);
    float var = s2 * (1.0f / 128.0f) - mu * mu;
    float o = (v - mu) * rsqrtf(var + 1e-5f) * gam[c] + bet[c];
    g_h[(long)n * 128 + c] = fmaxf(o, 0.0f);
}

// ---------------- final tiny head: out = z @ w2^T + b2 -----------------------
__global__ void head2(const float* __restrict__ w2, const float* __restrict__ b2,
                      float* __restrict__ out) {
    int gw = (blockIdx.x * blockDim.x + threadIdx.x) >> 5;
    if (gw >= NNODES) return;
    int lane = threadIdx.x & 31;
    float4 zv = *reinterpret_cast<const float4*>(g_z + (long)gw * 128 + lane * 4);
    float4 w0 = *reinterpret_cast<const float4*>(w2 + lane * 4);
    float4 w1 = *reinterpret_cast<const float4*>(w2 + 128 + lane * 4);
    float p0 = zv.x * w0.x + zv.y * w0.y + zv.z * w0.z + zv.w * w0.w;
    float p1 = zv.x * w1.x + zv.y * w1.y + zv.z * w1.z + zv.w * w1.w;
#pragma unroll
    for (int o = 16; o; o >>= 1) {
        p0 += __shfl_xor_sync(0xffffffffu, p0, o);
        p1 += __shfl_xor_sync(0xffffffffu, p1, o);
    }
    if (lane == 0) {
        out[gw * 2 + 0] = p0 + b2[0];
        out[gw * 2 + 1] = p1 + b2[1];
    }
}

// ---------------- host orchestration -----------------------------------------
extern "C" void kernel_launch(void* const* d_in, const int* in_sizes, int n_in,
                              void* d_out, int out_size) {
    const int*   x_type  = (const int*)d_in[0];
    const int*   x_tok   = (const int*)d_in[1];
    const float* x_small = (const float*)d_in[2];
    const int*   ei      = (const int*)d_in[3];
    const int*   et      = (const int*)d_in[4];
    const float* conv_w  = (const float*)d_in[5];
    const float* wih     = (const float*)d_in[6];
    const float* whh     = (const float*)d_in[7];
    const float* bih     = (const float*)d_in[8];
    const float* bhh     = (const float*)d_in[9];
    const float* ln_g    = (const float*)d_in[10];
    const float* ln_b    = (const float*)d_in[11];
    const float* hw1     = (const float*)d_in[12];
    const float* hb1     = (const float*)d_in[13];
    const float* hw2     = (const float*)d_in[14];
    const float* hb2     = (const float*)d_in[15];
    float* out = (float*)d_out;

    float *h_, *m_, *x_, *agg_, *tot_, *gi_, *gh_, *z_;
    cudaGetSymbolAddress((void**)&h_,   g_h);
    cudaGetSymbolAddress((void**)&m_,   g_m);
    cudaGetSymbolAddress((void**)&x_,   g_x);
    cudaGetSymbolAddress((void**)&agg_, g_agg);
    cudaGetSymbolAddress((void**)&tot_, g_tot);
    cudaGetSymbolAddress((void**)&gi_,  g_gi);
    cudaGetSymbolAddress((void**)&gh_,  g_gh);
    cudaGetSymbolAddress((void**)&z_,   g_z);

    const size_t NC_BYTES = (size_t)NNODES * CDIM * sizeof(float);
    const int NC_GRID = (NNODES * CDIM + 255) / 256;

    build_features<<<NC_GRID, 256>>>(x_type, x_tok, x_small);

    dim3 g1((NNODES + 127) / 128, 1);
    dim3 g3((NNODES + 127) / 128, 3);
    const int SC_GRID = (int)(((long)NEDGES * 32 + 255) / 256);

    for (int b = 0; b < 2; b++) {
        cudaMemsetAsync(tot_, 0, NC_BYTES);
        for (int t = 0; t < 3; t++) {
            cudaMemcpyAsync(m_, h_, NC_BYTES, cudaMemcpyDeviceToDevice);
            for (int s = 0; s < 3; s++) {
                const float* W = conv_w + (size_t)(((b * 3) + t) * 3 + s) * 128 * 128;
                sgemm128<0, 0><<<g1, 256>>>(m_, W, nullptr, x_, NNODES, 128);
                cudaMemsetAsync(agg_, 0, NC_BYTES);
                scatter_add<<<SC_GRID, 256>>>(ei, et, t);
                const float* Wih = wih + (size_t)(b * 3 + t) * K3C * 128;
                const float* Whh = whh + (size_t)(b * 3 + t) * K3C * 128;
                const float* Bih = bih + (size_t)(b * 3 + t) * K3C;
                const float* Bhh = bhh + (size_t)(b * 3 + t) * K3C;
                sgemm128<1, 0><<<g3, 256>>>(agg_, Wih, Bih, gi_, NNODES, K3C);
                sgemm128<1, 0><<<g3, 256>>>(m_,   Whh, Bhh, gh_, NNODES, K3C);
                gru_gate<<<NC_GRID, 256>>>();
            }
            add_total<<<NC_GRID, 256>>>();
        }
        ln_relu<<<NNODES, 128>>>(ln_g + b * 128, ln_b + b * 128);
    }

    sgemm128<1, 1><<<g1, 256>>>(h_, hw1, hb1, z_, NNODES, 128);
    head2<<<(NNODES * 32 + 255) / 256, 256>>>(hw2, hb2, out);
}

// round 4
// speedup vs baseline: 1.3282x; 1.3282x over previous
#include <cuda_runtime.h>
#include <math.h>

#define NNODES 50000
#define NEDGES 500000
#define CDIM   128
#define K3C    384

typedef unsigned long long ull;

// ---------------- scratch (device globals; no allocations allowed) ----------
__device__ float g_h  [NNODES * CDIM];
__device__ float g_m  [NNODES * CDIM];
__device__ float g_x  [NNODES * CDIM];
__device__ float g_agg[NNODES * CDIM];
__device__ float g_tot[NNODES * CDIM];
__device__ float g_gi [NNODES * K3C];
__device__ float g_gh [NNODES * K3C];
__device__ float g_z  [NNODES * CDIM];
// edge bucketing
__device__ int g_cnt[3];
__device__ int g_off[4];
__device__ int g_cur[3];
__device__ int g_es [NEDGES];
__device__ int g_ed [NEDGES];

// ---------------- f32x2 helpers ----------------------------------------------
__device__ __forceinline__ void ffma2(ull& c, ull a, ull b) {
    asm("fma.rn.f32x2 %0, %1, %2, %0;" : "+l"(c) : "l"(a), "l"(b));
}
__device__ __forceinline__ ull pack2(float x, float y) {
    ull r;
    asm("mov.b64 %0, {%1, %2};" : "=l"(r) : "f"(x), "f"(y));
    return r;
}
__device__ __forceinline__ float2 unpack2(ull v) {
    float x, y;
    asm("mov.b64 {%0, %1}, %2;" : "=f"(x), "=f"(y) : "l"(v));
    return make_float2(x, y);
}

// ---------------- feature build ---------------------------------------------
__global__ void build_features(const int* __restrict__ xt,
                               const int* __restrict__ xtok,
                               const float* __restrict__ xs) {
    int idx = blockIdx.x * blockDim.x + threadIdx.x;
    if (idx >= NNODES * CDIM) return;
    int n = idx >> 7;
    int c = idx & 127;
    float v;
    if (c < 32) {
        v = (c == xt[n]) ? 1.0f : 0.0f;
    } else if (c < 126) {
        int tok = xtok[n];
        tok = min(max(tok, 0), 93);
        v = ((c - 32) == tok) ? 1.0f : 0.0f;
    } else {
        v = xs[n * 2 + (c - 126)];
    }
    g_h[idx] = v;
}

// ---------------- fp32 SGEMM (f32x2 packed FMA), K=128 fixed -----------------
// TRANSB=0: B is [128, Ncols] row-major (C = A*B)
// TRANSB=1: B is [Ncols, 128] row-major (C = A*B^T); Ncols multiple of 128.
#define ASTR 132
#define BSTR 132

template <int TRANSB, int RELU>
__global__ __launch_bounds__(256)
void sgemm128(const float* __restrict__ A, const float* __restrict__ B,
              const float* __restrict__ bias, float* __restrict__ C,
              int M, int Ncols) {
    __shared__ __align__(16) float As[2][16][ASTR];
    __shared__ __align__(16) float Bs[2][16][BSTR];
    const int tid  = threadIdx.x;
    const int brow = blockIdx.x * 128;
    const int bcol = blockIdx.y * 128;
    const int trow = (tid >> 4) * 8;
    const int tc   = (tid & 15) * 4;   // columns tc..tc+3 and tc+64..tc+67

    ull acc[8][4];
#pragma unroll
    for (int i = 0; i < 8; i++)
#pragma unroll
        for (int j = 0; j < 4; j++) acc[i][j] = 0ULL;

    float4 pa[2], pb[2];

    // ---- tile loaders (global -> regs) ----
    auto loadA = [&](int kt) {
#pragma unroll
        for (int i = 0; i < 2; i++) {
            int q  = tid + 256 * i;
            int r  = q >> 2;
            int c4 = (q & 3) * 4;
            int gr = brow + r;
            pa[i] = (gr < M) ? *reinterpret_cast<const float4*>(A + (long)gr * 128 + kt + c4)
                             : make_float4(0.f, 0.f, 0.f, 0.f);
        }
    };
    auto loadB = [&](int kt) {
#pragma unroll
        for (int i = 0; i < 2; i++) {
            int q = tid + 256 * i;
            if (TRANSB) {
                int j  = q >> 2;
                int c4 = (q & 3) * 4;
                pb[i] = *reinterpret_cast<const float4*>(B + (long)(bcol + j) * 128 + kt + c4);
            } else {
                int kr = q >> 5;
                int c4 = (q & 31) * 4;
                pb[i] = *reinterpret_cast<const float4*>(B + (long)(kt + kr) * Ncols + bcol + c4);
            }
        }
    };
    // ---- regs -> smem ----
    auto storeTile = [&](int buf) {
#pragma unroll
        for (int i = 0; i < 2; i++) {
            int q  = tid + 256 * i;
            int r  = q >> 2;
            int c4 = (q & 3) * 4;
            As[buf][c4 + 0][r] = pa[i].x;
            As[buf][c4 + 1][r] = pa[i].y;
            As[buf][c4 + 2][r] = pa[i].z;
            As[buf][c4 + 3][r] = pa[i].w;
            if (TRANSB) {
                int j = q >> 2;
                Bs[buf][c4 + 0][j] = pb[i].x;
                Bs[buf][c4 + 1][j] = pb[i].y;
                Bs[buf][c4 + 2][j] = pb[i].z;
                Bs[buf][c4 + 3][j] = pb[i].w;
            } else {
                int kr  = q >> 5;
                int cc4 = (q & 31) * 4;
                *reinterpret_cast<float4*>(&Bs[buf][kr][cc4]) = pb[i];
            }
        }
    };

    loadA(0); loadB(0);
    storeTile(0);
    __syncthreads();

#pragma unroll 1
    for (int kt = 0; kt < 8; kt++) {
        int cur = kt & 1;
        if (kt < 7) { loadA((kt + 1) * 16); loadB((kt + 1) * 16); }
#pragma unroll
        for (int k = 0; k < 16; k++) {
            float4 a0 = *reinterpret_cast<const float4*>(&As[cur][k][trow]);
            float4 a1 = *reinterpret_cast<const float4*>(&As[cur][k][trow + 4]);
            float4 b0 = *reinterpret_cast<const float4*>(&Bs[cur][k][tc]);
            float4 b1 = *reinterpret_cast<const float4*>(&Bs[cur][k][tc + 64]);
            ull bb0 = pack2(b0.x, b0.y);
            ull bb1 = pack2(b0.z, b0.w);
            ull bb2 = pack2(b1.x, b1.y);
            ull bb3 = pack2(b1.z, b1.w);
            float av[8] = {a0.x, a0.y, a0.z, a0.w, a1.x, a1.y, a1.z, a1.w};
#pragma unroll
            for (int i = 0; i < 8; i++) {
                ull aa = pack2(av[i], av[i]);
                ffma2(acc[i][0], aa, bb0);
                ffma2(acc[i][1], aa, bb1);
                ffma2(acc[i][2], aa, bb2);
                ffma2(acc[i][3], aa, bb3);
            }
        }
        if (kt < 7) storeTile((kt + 1) & 1);
        __syncthreads();
    }

    // ---- epilogue ----
    float bia[8];
    if (bias != nullptr) {
#pragma unroll
        for (int j = 0; j < 4; j++) {
            bia[j]     = bias[bcol + tc + j];
            bia[4 + j] = bias[bcol + 64 + tc + j];
        }
    } else {
#pragma unroll
        for (int j = 0; j < 8; j++) bia[j] = 0.0f;
    }
#pragma unroll
    for (int i = 0; i < 8; i++) {
        int gr = brow + trow + i;
        if (gr >= M) break;
        float2 c01 = unpack2(acc[i][0]);
        float2 c23 = unpack2(acc[i][1]);
        float2 c45 = unpack2(acc[i][2]);
        float2 c67 = unpack2(acc[i][3]);
        float4 v0 = make_float4(c01.x + bia[0], c01.y + bia[1], c23.x + bia[2], c23.y + bia[3]);
        float4 v1 = make_float4(c45.x + bia[4], c45.y + bia[5], c67.x + bia[6], c67.y + bia[7]);
        if (RELU) {
            v0.x = fmaxf(v0.x, 0.f); v0.y = fmaxf(v0.y, 0.f);
            v0.z = fmaxf(v0.z, 0.f); v0.w = fmaxf(v0.w, 0.f);
            v1.x = fmaxf(v1.x, 0.f); v1.y = fmaxf(v1.y, 0.f);
            v1.z = fmaxf(v1.z, 0.f); v1.w = fmaxf(v1.w, 0.f);
        }
        *reinterpret_cast<float4*>(C + (long)gr * Ncols + bcol + tc)      = v0;
        *reinterpret_cast<float4*>(C + (long)gr * Ncols + bcol + 64 + tc) = v1;
    }
}

// ---------------- edge bucketing by type (once per launch) -------------------
__global__ void count_et(const int* __restrict__ et) {
    int e = blockIdx.x * blockDim.x + threadIdx.x;
    if (e < NEDGES) atomicAdd(&g_cnt[et[e]], 1);
}
__global__ void prefix_et() {
    g_off[0] = 0;
    g_off[1] = g_cnt[0];
    g_off[2] = g_cnt[0] + g_cnt[1];
    g_off[3] = g_cnt[0] + g_cnt[1] + g_cnt[2];
    g_cur[0] = 0;
    g_cur[1] = g_cnt[0];
    g_cur[2] = g_cnt[0] + g_cnt[1];
}
__global__ void bucket_et(const int* __restrict__ ei, const int* __restrict__ et) {
    int e = blockIdx.x * blockDim.x + threadIdx.x;
    if (e >= NEDGES) return;
    int t = et[e];
    int p = atomicAdd(&g_cur[t], 1);
    g_es[p] = ei[e];
    g_ed[p] = ei[NEDGES + e];
}

// ---------------- scatter-add over bucketed edges ----------------------------
__global__ void scatter_add(int t) {
    long idx = (long)blockIdx.x * blockDim.x + threadIdx.x;
    int e = (int)(idx >> 5);
    int lo = g_off[t], hi = g_off[t + 1];
    if (e < lo || e >= hi) return;
    int lane = (int)(idx & 31);
    int s = g_es[e];
    int d = g_ed[e];
    float4 v = *reinterpret_cast<const float4*>(g_x + (long)s * 128 + lane * 4);
    float* o = g_agg + (long)d * 128 + lane * 4;
    atomicAdd(o + 0, v.x);
    atomicAdd(o + 1, v.y);
    atomicAdd(o + 2, v.z);
    atomicAdd(o + 3, v.w);
}

// ---------------- GRU gate (r,z,n) + optional total accumulation -------------
__global__ void gru_gate(int addTot) {
    int idx = blockIdx.x * blockDim.x + threadIdx.x;      // over N*32 quads
    if (idx >= NNODES * 32) return;
    int n  = idx >> 5;
    int c4 = (idx & 31) * 4;
    const float* gi = g_gi + (long)n * K3C;
    const float* gh = g_gh + (long)n * K3C;
    float4 gir = *reinterpret_cast<const float4*>(gi + c4);
    float4 ghr = *reinterpret_cast<const float4*>(gh + c4);
    float4 giz = *reinterpret_cast<const float4*>(gi + 128 + c4);
    float4 ghz = *reinterpret_cast<const float4*>(gh + 128 + c4);
    float4 gin = *reinterpret_cast<const float4*>(gi + 256 + c4);
    float4 ghn = *reinterpret_cast<const float4*>(gh + 256 + c4);
    float4 hv  = *reinterpret_cast<const float4*>(g_m + (long)n * 128 + c4);
    float4 res;
#pragma unroll
    for (int j = 0; j < 4; j++) {
        float gi_r = (&gir.x)[j], gh_r = (&ghr.x)[j];
        float gi_z = (&giz.x)[j], gh_z = (&ghz.x)[j];
        float gi_n = (&gin.x)[j], gh_n = (&ghn.x)[j];
        float h    = (&hv.x)[j];
        float r  = 1.0f / (1.0f + expf(-(gi_r + gh_r)));
        float z  = 1.0f / (1.0f + expf(-(gi_z + gh_z)));
        float ng = tanhf(gi_n + r * gh_n);
        (&res.x)[j] = (1.0f - z) * ng + z * h;
    }
    *reinterpret_cast<float4*>(g_m + (long)n * 128 + c4) = res;
    if (addTot) {
        float4 tv = *reinterpret_cast<const float4*>(g_tot + (long)n * 128 + c4);
        tv.x += res.x; tv.y += res.y; tv.z += res.z; tv.w += res.w;
        *reinterpret_cast<float4*>(g_tot + (long)n * 128 + c4) = tv;
    }
}

// ---------------- LayerNorm(residual) + ReLU ---------------------------------
__global__ void ln_relu(const float* __restrict__ gam, const float* __restrict__ bet) {
    int n = blockIdx.x;
    int c = threadIdx.x;
    float v  = g_h[(long)n * 128 + c] + g_tot[(long)n * 128 + c];
    float s  = v;
    float s2 = v * v;
#pragma unroll
    for (int o = 16; o; o >>= 1) {
        s  += __shfl_xor_sync(0xffffffffu, s,  o);
        s2 += __shfl_xor_sync(0xffffffffu, s2, o);
    }
    __shared__ float sh[4], sh2[4];
    int w = c >> 5;
    if ((c & 31) == 0) { sh[w] = s; sh2[w] = s2; }
    __syncthreads();
    s  = sh[0] + sh[1] + sh[2] + sh[3];
    s2 = sh2[0] + sh2[1] + sh2[2] + sh2[3];
    float mu  = s * (1.0f / 128.0f);
    float var = s2 * (1.0f / 128.0f) - mu * mu;
    float o = (v - mu) * rsqrtf(var + 1e-5f) * gam[c] + bet[c];
    g_h[(long)n * 128 + c] = fmaxf(o, 0.0f);
}

// ---------------- final tiny head: out = z @ w2^T + b2 -----------------------
__global__ void head2(const float* __restrict__ w2, const float* __restrict__ b2,
                      float* __restrict__ out) {
    int gw = (blockIdx.x * blockDim.x + threadIdx.x) >> 5;
    if (gw >= NNODES) return;
    int lane = threadIdx.x & 31;
    float4 zv = *reinterpret_cast<const float4*>(g_z + (long)gw * 128 + lane * 4);
    float4 w0 = *reinterpret_cast<const float4*>(w2 + lane * 4);
    float4 w1 = *reinterpret_cast<const float4*>(w2 + 128 + lane * 4);
    float p0 = zv.x * w0.x + zv.y * w0.y + zv.z * w0.z + zv.w * w0.w;
    float p1 = zv.x * w1.x + zv.y * w1.y + zv.z * w1.z + zv.w * w1.w;
#pragma unroll
    for (int o = 16; o; o >>= 1) {
        p0 += __shfl_xor_sync(0xffffffffu, p0, o);
        p1 += __shfl_xor_sync(0xffffffffu, p1, o);
    }
    if (lane == 0) {
        out[gw * 2 + 0] = p0 + b2[0];
        out[gw * 2 + 1] = p1 + b2[1];
    }
}

// ---------------- host orchestration -----------------------------------------
extern "C" void kernel_launch(void* const* d_in, const int* in_sizes, int n_in,
                              void* d_out, int out_size) {
    const int*   x_type  = (const int*)d_in[0];
    const int*   x_tok   = (const int*)d_in[1];
    const float* x_small = (const float*)d_in[2];
    const int*   ei      = (const int*)d_in[3];
    const int*   et      = (const int*)d_in[4];
    const float* conv_w  = (const float*)d_in[5];
    const float* wih     = (const float*)d_in[6];
    const float* whh     = (const float*)d_in[7];
    const float* bih     = (const float*)d_in[8];
    const float* bhh     = (const float*)d_in[9];
    const float* ln_g    = (const float*)d_in[10];
    const float* ln_b    = (const float*)d_in[11];
    const float* hw1     = (const float*)d_in[12];
    const float* hb1     = (const float*)d_in[13];
    const float* hw2     = (const float*)d_in[14];
    const float* hb2     = (const float*)d_in[15];
    float* out = (float*)d_out;

    float *h_, *m_, *x_, *agg_, *tot_, *gi_, *gh_, *z_;
    int *cnt_;
    cudaGetSymbolAddress((void**)&h_,   g_h);
    cudaGetSymbolAddress((void**)&m_,   g_m);
    cudaGetSymbolAddress((void**)&x_,   g_x);
    cudaGetSymbolAddress((void**)&agg_, g_agg);
    cudaGetSymbolAddress((void**)&tot_, g_tot);
    cudaGetSymbolAddress((void**)&gi_,  g_gi);
    cudaGetSymbolAddress((void**)&gh_,  g_gh);
    cudaGetSymbolAddress((void**)&z_,   g_z);
    cudaGetSymbolAddress((void**)&cnt_, g_cnt);

    const size_t NC_BYTES = (size_t)NNODES * CDIM * sizeof(float);
    const int NC_GRID  = (NNODES * CDIM + 255) / 256;
    const int NQ_GRID  = (NNODES * 32 + 255) / 256;
    const int E_GRID   = (NEDGES + 255) / 256;
    const int SC_GRID  = (int)(((long)NEDGES * 32 + 255) / 256);

    build_features<<<NC_GRID, 256>>>(x_type, x_tok, x_small);

    // bucket edges by type (deterministic w.r.t. final sums)
    cudaMemsetAsync(cnt_, 0, 3 * sizeof(int));
    count_et<<<E_GRID, 256>>>(et);
    prefix_et<<<1, 1>>>();
    bucket_et<<<E_GRID, 256>>>(ei, et);

    dim3 g1((NNODES + 127) / 128, 1);
    dim3 g3((NNODES + 127) / 128, 3);

    for (int b = 0; b < 2; b++) {
        cudaMemsetAsync(tot_, 0, NC_BYTES);
        for (int t = 0; t < 3; t++) {
            cudaMemcpyAsync(m_, h_, NC_BYTES, cudaMemcpyDeviceToDevice);
            for (int s = 0; s < 3; s++) {
                const float* W = conv_w + (size_t)(((b * 3) + t) * 3 + s) * 128 * 128;
                sgemm128<0, 0><<<g1, 256>>>(m_, W, nullptr, x_, NNODES, 128);
                cudaMemsetAsync(agg_, 0, NC_BYTES);
                scatter_add<<<SC_GRID, 256>>>(t);
                const float* Wih = wih + (size_t)(b * 3 + t) * K3C * 128;
                const float* Whh = whh + (size_t)(b * 3 + t) * K3C * 128;
                const float* Bih = bih + (size_t)(b * 3 + t) * K3C;
                const float* Bhh = bhh + (size_t)(b * 3 + t) * K3C;
                sgemm128<1, 0><<<g3, 256>>>(agg_, Wih, Bih, gi_, NNODES, K3C);
                sgemm128<1, 0><<<g3, 256>>>(m_,   Whh, Bhh, gh_, NNODES, K3C);
                gru_gate<<<NQ_GRID, 256>>>(s == 2 ? 1 : 0);
            }
        }
        ln_relu<<<NNODES, 128>>>(ln_g + b * 128, ln_b + b * 128);
    }

    sgemm128<1, 1><<<g1, 256>>>(h_, hw1, hb1, z_, NNODES, 128);
    head2<<<(NNODES * 32 + 255) / 256, 256>>>(hw2, hb2, out);
}